// round 1
// baseline (speedup 1.0000x reference)
#include <cuda_runtime.h>
#include <cstdint>

// ----------------------------------------------------------------------------
// ResBlock_71021579207010 — GB300 (sm_103a)
//
// Reference collapses: ste_sign(relu(.)) == +1, so conv1/bn1 are dead and
// conv2 output is a per-channel constant (two variants: t<16 pad region vs
// t>=16). Remaining data-dependent work is the k=1 binarized shortcut GEMM:
//   out[b,t,f] = relu( c[f, t<16] + sum_c sign(x[b,t,c]) * sign(w_sc[c,f]) )
// Binary dot via ballot-packed bits + xor/popc: dot = 128 - 2*popc(px^pw).
//
// Shapes: B=32, T=8192, C=F=128, rows = B*T = 262144.
// ----------------------------------------------------------------------------

__device__ __align__(16) unsigned g_pw[128][4];     // packed sign bits of w_sc per f
__device__ __align__(16) float    g_add_ge[128];    // relu(bn2(S0+S1)) + 128
__device__ __align__(16) float    g_add_lt[128];    // relu(bn2(S1))    + 128

// One block of 128 threads; thread f builds its constants + packed weights.
__global__ void prologue_kernel(const float* __restrict__ w2,
                                const float* __restrict__ w_sc,
                                const float* __restrict__ beta2,
                                const float* __restrict__ mean2,
                                const float* __restrict__ var2)
{
    const int f = threadIdx.x;  // 0..127

    // S_k[f] = sum_c sign(w2[k,c,f]);  w2 is [2,128,128] row-major
    float S0 = 0.f, S1 = 0.f;
    #pragma unroll 4
    for (int c = 0; c < 128; ++c) {
        S0 += (w2[c * 128 + f]             >= 0.f) ? 1.f : -1.f;
        S1 += (w2[128 * 128 + c * 128 + f] >= 0.f) ? 1.f : -1.f;
    }
    const float inv = rsqrtf(var2[f] + 1e-3f);
    const float cge = fmaxf(fmaf(S0 + S1 - mean2[f], inv, beta2[f]), 0.f);
    const float clt = fmaxf(fmaf(S1      - mean2[f], inv, beta2[f]), 0.f);
    g_add_ge[f] = cge + 128.f;   // fold the "+128" of dot = 128 - 2*pc
    g_add_lt[f] = clt + 128.f;

    // Pack sign bits of w_sc[:,f] to match the main kernel's ballot order:
    // word j, bit l  <->  channel c = 4*l + j.   w_sc is [1,128,128]: idx c*128+f.
    unsigned p0 = 0u, p1 = 0u, p2 = 0u, p3 = 0u;
    #pragma unroll
    for (int l = 0; l < 32; ++l) {
        if (w_sc[(4 * l + 0) * 128 + f] >= 0.f) p0 |= (1u << l);
        if (w_sc[(4 * l + 1) * 128 + f] >= 0.f) p1 |= (1u << l);
        if (w_sc[(4 * l + 2) * 128 + f] >= 0.f) p2 |= (1u << l);
        if (w_sc[(4 * l + 3) * 128 + f] >= 0.f) p3 |= (1u << l);
    }
    g_pw[f][0] = p0; g_pw[f][1] = p1; g_pw[f][2] = p2; g_pw[f][3] = p3;
}

// Main kernel: 2048 blocks x 256 threads. Each warp owns 16 rows; each lane
// owns 4 consecutive f outputs (float4 store). Weights/consts hoisted into
// registers before the row loop — no shared memory, no LDS in the hot loop.
__global__ void __launch_bounds__(256) resblock_main(const float* __restrict__ x,
                                                     float* __restrict__ out)
{
    const int lane = threadIdx.x & 31;
    const int warp = threadIdx.x >> 5;
    const int f0   = 4 * lane;

    // Per-lane weight columns (row-invariant): 16 u32 + 8 floats in registers.
    const uint4 pw0 = *reinterpret_cast<const uint4*>(g_pw[f0 + 0]);
    const uint4 pw1 = *reinterpret_cast<const uint4*>(g_pw[f0 + 1]);
    const uint4 pw2 = *reinterpret_cast<const uint4*>(g_pw[f0 + 2]);
    const uint4 pw3 = *reinterpret_cast<const uint4*>(g_pw[f0 + 3]);
    const float4 age = *reinterpret_cast<const float4*>(&g_add_ge[f0]);
    const float4 alt = *reinterpret_cast<const float4*>(&g_add_lt[f0]);

    const size_t row0 = (size_t)blockIdx.x * 128 + (size_t)warp * 16;

    #pragma unroll 4
    for (int r = 0; r < 16; ++r) {
        const size_t row = row0 + r;

        // 128 floats of this row: lane reads channels [4*lane, 4*lane+3].
        const float4 v = reinterpret_cast<const float4*>(x + row * 128)[lane];

        // Pack row sign bits: word j, bit l = sign(x[4l + j])  (>=0 -> 1).
        const unsigned px0 = __ballot_sync(0xffffffffu, v.x >= 0.f);
        const unsigned px1 = __ballot_sync(0xffffffffu, v.y >= 0.f);
        const unsigned px2 = __ballot_sync(0xffffffffu, v.z >= 0.f);
        const unsigned px3 = __ballot_sync(0xffffffffu, v.w >= 0.f);

        // Causal-pad region of conv2: t = row % 8192 < 16 uses the S1-only const.
        const bool lt = ((row & 8191u) < 16u);
        const float a0 = lt ? alt.x : age.x;
        const float a1 = lt ? alt.y : age.y;
        const float a2 = lt ? alt.z : age.z;
        const float a3 = lt ? alt.w : age.w;

        const int pc0 = __popc(px0 ^ pw0.x) + __popc(px1 ^ pw0.y)
                      + __popc(px2 ^ pw0.z) + __popc(px3 ^ pw0.w);
        const int pc1 = __popc(px0 ^ pw1.x) + __popc(px1 ^ pw1.y)
                      + __popc(px2 ^ pw1.z) + __popc(px3 ^ pw1.w);
        const int pc2 = __popc(px0 ^ pw2.x) + __popc(px1 ^ pw2.y)
                      + __popc(px2 ^ pw2.z) + __popc(px3 ^ pw2.w);
        const int pc3 = __popc(px0 ^ pw3.x) + __popc(px1 ^ pw3.y)
                      + __popc(px2 ^ pw3.z) + __popc(px3 ^ pw3.w);

        float4 o;
        o.x = fmaxf(fmaf(-2.f, (float)pc0, a0), 0.f);
        o.y = fmaxf(fmaf(-2.f, (float)pc1, a1), 0.f);
        o.z = fmaxf(fmaf(-2.f, (float)pc2, a2), 0.f);
        o.w = fmaxf(fmaf(-2.f, (float)pc3, a3), 0.f);

        reinterpret_cast<float4*>(out + row * 128)[lane] = o;
    }
}

extern "C" void kernel_launch(void* const* d_in, const int* in_sizes, int n_in,
                              void* d_out, int out_size)
{
    // metadata order: x, w1, w2, w_sc, beta1, mean1, var1, beta2, mean2, var2
    const float* x     = (const float*)d_in[0];
    const float* w2    = (const float*)d_in[2];
    const float* w_sc  = (const float*)d_in[3];
    const float* beta2 = (const float*)d_in[7];
    const float* mean2 = (const float*)d_in[8];
    const float* var2  = (const float*)d_in[9];
    float* out = (float*)d_out;

    prologue_kernel<<<1, 128>>>(w2, w_sc, beta2, mean2, var2);
    // 262144 rows / 128 rows per block = 2048 blocks
    resblock_main<<<2048, 256>>>(x, out);
}

// round 3
// speedup vs baseline: 1.3419x; 1.3419x over previous
#include <cuda_runtime.h>
#include <cstdint>

// ----------------------------------------------------------------------------
// ResBlock_71021579207010 — GB300 (sm_103a)
//
// Reference collapses: ste_sign(relu(.)) == +1, so conv1/bn1 are dead and
// conv2 output is a per-channel constant (two variants: t<16 pad region vs
// t>=16). Remaining data-dependent work is the k=1 binarized shortcut GEMM:
//   out[b,t,f] = relu( c[f, t<16] + sum_c sign(x[b,t,c]) * sign(w_sc[c,f]) )
// Binary dot via ballot-packed bits + xor/popc: dot = 128 - 2*popc(px^pw).
//
// Shapes: B=32, T=8192, C=F=128, rows = B*T = 262144.
// R1 fix: prologue was 1 block x 128 thr (MLP-starved, ~27us). Now 1024 thr,
// segment-parallel with smem reduction (~2-3us).
// R2: resubmit unchanged (broker timeout, no data).
// ----------------------------------------------------------------------------

__device__ __align__(16) unsigned g_pw[128][4];     // packed sign bits of w_sc per f
__device__ __align__(16) float    g_add_ge[128];    // relu(bn2(S0+S1)) + 128
__device__ __align__(16) float    g_add_lt[128];    // relu(bn2(S1))    + 128

// One block, 1024 threads. tid = seg*128 + f, seg in 0..7.
// Each seg sums 16 c-rows of w2 for both k; segs 0..3 also pack one w_sc word.
__global__ void __launch_bounds__(1024) prologue_kernel(
    const float* __restrict__ w2,
    const float* __restrict__ w_sc,
    const float* __restrict__ beta2,
    const float* __restrict__ mean2,
    const float* __restrict__ var2)
{
    const int tid = threadIdx.x;
    const int f   = tid & 127;
    const int seg = tid >> 7;   // 0..7

    __shared__ int sh0[8][128];
    __shared__ int sh1[8][128];

    // Sign-count over 16 channels per segment (coalesced in f across the warp).
    const int c0 = seg * 16;
    int cnt0 = 0, cnt1 = 0;
    #pragma unroll
    for (int i = 0; i < 16; ++i) {
        const int c = c0 + i;
        cnt0 += (w2[c * 128 + f]         >= 0.f) ? 1 : 0;
        cnt1 += (w2[16384 + c * 128 + f] >= 0.f) ? 1 : 0;
    }
    sh0[seg][f] = cnt0;
    sh1[seg][f] = cnt1;

    // Pack sign bits of w_sc[:,f], word j = seg (segs 0..3):
    // word j, bit l  <->  channel c = 4*l + j.   w_sc is [1,128,128]: idx c*128+f.
    if (seg < 4) {
        unsigned p = 0u;
        #pragma unroll
        for (int l = 0; l < 32; ++l) {
            if (w_sc[(4 * l + seg) * 128 + f] >= 0.f) p |= (1u << l);
        }
        g_pw[f][seg] = p;
    }
    __syncthreads();

    if (seg == 0) {
        int t0 = 0, t1 = 0;
        #pragma unroll
        for (int s = 0; s < 8; ++s) { t0 += sh0[s][f]; t1 += sh1[s][f]; }
        const float S0 = 2.f * (float)t0 - 128.f;   // sum of signs, k=0
        const float S1 = 2.f * (float)t1 - 128.f;   // k=1
        const float inv = rsqrtf(var2[f] + 1e-3f);
        const float cge = fmaxf(fmaf(S0 + S1 - mean2[f], inv, beta2[f]), 0.f);
        const float clt = fmaxf(fmaf(S1      - mean2[f], inv, beta2[f]), 0.f);
        g_add_ge[f] = cge + 128.f;   // fold the "+128" of dot = 128 - 2*pc
        g_add_lt[f] = clt + 128.f;
    }
}

// Row-loop body shared by both paths. HAS_LT selects per-row pad handling.
template <bool HAS_LT>
__device__ __forceinline__ void do_rows(const float* __restrict__ x,
                                        float* __restrict__ out,
                                        size_t row0, int lane,
                                        const uint4& pw0, const uint4& pw1,
                                        const uint4& pw2, const uint4& pw3,
                                        const float4& age, const float4& alt)
{
    #pragma unroll 8
    for (int r = 0; r < 16; ++r) {
        const size_t row = row0 + r;

        // 128 floats of this row: lane reads channels [4*lane, 4*lane+3].
        const float4 v = reinterpret_cast<const float4*>(x + row * 128)[lane];

        // Pack row sign bits: word j, bit l = sign(x[4l + j])  (>=0 -> 1).
        const unsigned px0 = __ballot_sync(0xffffffffu, v.x >= 0.f);
        const unsigned px1 = __ballot_sync(0xffffffffu, v.y >= 0.f);
        const unsigned px2 = __ballot_sync(0xffffffffu, v.z >= 0.f);
        const unsigned px3 = __ballot_sync(0xffffffffu, v.w >= 0.f);

        float a0, a1, a2, a3;
        if (HAS_LT) {
            const bool lt = ((row & 8191u) < 16u);  // conv2 causal pad region
            a0 = lt ? alt.x : age.x;
            a1 = lt ? alt.y : age.y;
            a2 = lt ? alt.z : age.z;
            a3 = lt ? alt.w : age.w;
        } else {
            a0 = age.x; a1 = age.y; a2 = age.z; a3 = age.w;
        }

        const int pc0 = __popc(px0 ^ pw0.x) + __popc(px1 ^ pw0.y)
                      + __popc(px2 ^ pw0.z) + __popc(px3 ^ pw0.w);
        const int pc1 = __popc(px0 ^ pw1.x) + __popc(px1 ^ pw1.y)
                      + __popc(px2 ^ pw1.z) + __popc(px3 ^ pw1.w);
        const int pc2 = __popc(px0 ^ pw2.x) + __popc(px1 ^ pw2.y)
                      + __popc(px2 ^ pw2.z) + __popc(px3 ^ pw2.w);
        const int pc3 = __popc(px0 ^ pw3.x) + __popc(px1 ^ pw3.y)
                      + __popc(px2 ^ pw3.z) + __popc(px3 ^ pw3.w);

        float4 o;
        o.x = fmaxf(fmaf(-2.f, (float)pc0, a0), 0.f);
        o.y = fmaxf(fmaf(-2.f, (float)pc1, a1), 0.f);
        o.z = fmaxf(fmaf(-2.f, (float)pc2, a2), 0.f);
        o.w = fmaxf(fmaf(-2.f, (float)pc3, a3), 0.f);

        reinterpret_cast<float4*>(out + row * 128)[lane] = o;
    }
}

// Main kernel: 2048 blocks x 256 threads. Each warp owns 16 rows; each lane
// owns 4 consecutive f outputs (float4 load/store). Weights/consts hoisted
// into registers before the row loop — no smem, no LDS in the hot loop.
__global__ void __launch_bounds__(256) resblock_main(const float* __restrict__ x,
                                                     float* __restrict__ out)
{
    const int lane = threadIdx.x & 31;
    const int warp = threadIdx.x >> 5;
    const int f0   = 4 * lane;

    // Per-lane weight columns (row-invariant): 16 u32 + 8 floats in registers.
    const uint4 pw0 = *reinterpret_cast<const uint4*>(g_pw[f0 + 0]);
    const uint4 pw1 = *reinterpret_cast<const uint4*>(g_pw[f0 + 1]);
    const uint4 pw2 = *reinterpret_cast<const uint4*>(g_pw[f0 + 2]);
    const uint4 pw3 = *reinterpret_cast<const uint4*>(g_pw[f0 + 3]);
    const float4 age = *reinterpret_cast<const float4*>(&g_add_ge[f0]);
    const float4 alt = *reinterpret_cast<const float4*>(&g_add_lt[f0]);

    const size_t row0 = (size_t)blockIdx.x * 128 + (size_t)warp * 16;

    // Rows with t<16 exist only in warp 0 of every 64th block (8192/128 = 64).
    if (warp == 0 && (blockIdx.x & 63) == 0) {
        do_rows<true >(x, out, row0, lane, pw0, pw1, pw2, pw3, age, alt);
    } else {
        do_rows<false>(x, out, row0, lane, pw0, pw1, pw2, pw3, age, alt);
    }
}

extern "C" void kernel_launch(void* const* d_in, const int* in_sizes, int n_in,
                              void* d_out, int out_size)
{
    // metadata order: x, w1, w2, w_sc, beta1, mean1, var1, beta2, mean2, var2
    const float* x     = (const float*)d_in[0];
    const float* w2    = (const float*)d_in[2];
    const float* w_sc  = (const float*)d_in[3];
    const float* beta2 = (const float*)d_in[7];
    const float* mean2 = (const float*)d_in[8];
    const float* var2  = (const float*)d_in[9];
    float* out = (float*)d_out;

    prologue_kernel<<<1, 1024>>>(w2, w_sc, beta2, mean2, var2);
    // 262144 rows / 128 rows per block = 2048 blocks
    resblock_main<<<2048, 256>>>(x, out);
}